// round 13
// baseline (speedup 1.0000x reference)
#include <cuda_runtime.h>
#include <cuda_bf16.h>
#include <mma.h>
#include <math.h>

using namespace nvcuda;

#define BB 4
#define CC 256
#define OO 256
#define KK 2304          // C * 9
#define NPIX 16384
#define NCHUNK 36        // K chunks of 64
#define CHB 67584        // bytes per weight chunk (hi 64x528 + lo 64x528)
#define ALDB 264         // B leading dim in bf16 elements (528 B rows)
#define ALDA 72          // A chunk leading dim in bf16 elements (144 B rows)
#define ROWA 260         // k_offsets x-tile row stride (floats)

// k_mma smem bytes: A bufs 2x36864 | B bufs 2xCHB
#define SMB  73728
#define SMT  208896      // 73728 + 2*67584

// k_offsets smem (floats): sv0 0 | sv1 4160 | sw0 8320 | sw1 13440
#define OFF_SV1 4160
#define OFF_SW0 8320
#define OFF_TOT 18560    // 74240 B -> 3 CTAs/SM

// Static device scratch
__device__ float g_xT[BB * 4096 * CC];            // [b][hw][c]  16.8 MB
__device__ float g_woffT3[KK * 20];               // [k][ch pad 20]
__device__ float g_desc[NPIX * 9 * 8];            // per (pix,tap): wq f4 + oq i4
__device__ unsigned char g_wB[NCHUNK * CHB];      // bf16 hi/lo weight chunks

__device__ float g_mean[OO];
__device__ float g_scale[OO];

// ---- packed f32x2 helpers (offset kernel) ----
#define FMA2(d,a,b,c)  asm("fma.rn.f32x2 %0,%1,%2,%3;" : "=l"(d) : "l"(a),"l"(b),"l"(c))
#define PACK2(d,lo,hi) asm("mov.b64 %0,{%1,%2};" : "=l"(d) : "f"(lo),"f"(hi))
#define UNPACK2(lo,hi,s) asm("mov.b64 {%0,%1},%2;" : "=f"(lo),"=f"(hi) : "l"(s))

// ---- async copy ----
#define CPASYNC16(dst,src) asm volatile( \
    "cp.async.cg.shared.global [%0],[%1],16;" :: "r"(dst), "l"(src))
#define CPASYNC16Z(dst,src,sz) asm volatile( \
    "cp.async.cg.shared.global [%0],[%1],16,%2;" :: "r"(dst), "l"(src), "r"(sz))
#define CPCOMMIT() asm volatile("cp.async.commit_group;" ::: "memory")
#define CPWAIT(n)  asm volatile("cp.async.wait_group %0;" :: "n"(n) : "memory")

// ---------------------------------------------------------------------------
// transpose x [B][C][HW] -> xT [B][HW][C]
// ---------------------------------------------------------------------------
__global__ void k_transpose_x(const float* __restrict__ x) {
    __shared__ float tile[32][33];
    int b   = blockIdx.z;
    int hw0 = blockIdx.x * 32;
    int c0  = blockIdx.y * 32;
    tile[threadIdx.y][threadIdx.x] =
        x[(b * CC + c0 + threadIdx.y) * 4096 + hw0 + threadIdx.x];
    __syncthreads();
    g_xT[(b * 4096 + hw0 + threadIdx.y) * CC + c0 + threadIdx.x] =
        tile[threadIdx.x][threadIdx.y];
}

// ---------------------------------------------------------------------------
// transpose w_off [ch][c][tap] -> g_woffT3[(tap*256+c)*20 + ch]  (80B rows)
// ---------------------------------------------------------------------------
__global__ void k_transpose_woff(const float* __restrict__ w_off) {
    int idx = blockIdx.x * blockDim.x + threadIdx.x;
    if (idx >= 18 * CC * 9) return;
    int ch  = idx / (CC * 9);
    int r   = idx % (CC * 9);
    int c   = r / 9;
    int tap = r % 9;
    g_woffT3[(tap * CC + c) * 20 + ch] = w_off[idx];
}

// ---------------------------------------------------------------------------
// prep weights: w_def [o][c][tap] -> bf16 hi/lo chunks [k][o], 528B rows
// ---------------------------------------------------------------------------
__global__ void k_prep_w(const float* __restrict__ w_def) {
    int idx = blockIdx.x * blockDim.x + threadIdx.x;
    if (idx >= KK * OO) return;
    int o = idx & 255;
    int k = idx >> 8;
    int c = k & 255, tap = k >> 8;
    int ci = k >> 6, r = k & 63;
    float v = w_def[o * KK + c * 9 + tap];
    __nv_bfloat16 hb = __float2bfloat16_rn(v);
    float hf = __bfloat162float(hb);
    __nv_bfloat16 lb = __float2bfloat16_rn(v - hf);
    unsigned char* base = g_wB + (size_t)ci * CHB;
    *(__nv_bfloat16*)(base + r * 528 + o * 2) = hb;
    *(__nv_bfloat16*)(base + 33792 + r * 528 + o * 2) = lb;
}

// ---------------------------------------------------------------------------
// Offset conv + gather-descriptor kernel. 1024 blocks x 256 thr, 16 px/block,
// 3 CTAs/SM. Writes g_desc.
// ---------------------------------------------------------------------------
__global__ void __launch_bounds__(256, 3)
k_offsets(const float* __restrict__ b_off) {
    extern __shared__ float sm[];
    const int t    = threadIdx.x;
    const int pid0 = blockIdx.x * 16;
    const int b    = pid0 >> 12;
    const int hw0  = pid0 & 4095;
    const int h    = hw0 >> 6;
    const int w0   = hw0 & 63;          // 0,16,32,48
    const float* xb = g_xT + ((size_t)b << 20);
    unsigned smb = (unsigned)__cvta_generic_to_shared(sm);

    auto stage_x = [&](int tap, int buf) {
        int ty = tap / 3, kx = tap % 3 - 1;
        int y = h + ty - 1;
        bool yok = (unsigned)y < 64u;
        int yc = min(max(y, 0), 63);
        unsigned dbase = smb + (unsigned)(buf * OFF_SV1 * 4);
        #pragma unroll
        for (int u = 0; u < 4; u++) {
            int id = (u << 8) + t;          // 0..1023
            int px = id >> 6, seg = id & 63;
            int xx = w0 + px + kx;
            bool ok = yok && ((unsigned)xx < 64u);
            int xc = min(max(xx, 0), 63);
            const char* src = (const char*)(xb + (((yc << 6) + xc) << 8)) + (seg << 4);
            unsigned d = dbase + (unsigned)((px * ROWA + (seg << 2)) << 2);
            unsigned sz = ok ? 16u : 0u;
            CPASYNC16Z(d, src, sz);
        }
    };
    auto stage_w = [&](int tap, int buf) {
        const char* src = (const char*)(g_woffT3 + tap * 5120);
        unsigned dbase = smb + (unsigned)((OFF_SW0 + buf * 5120) * 4);
        #pragma unroll
        for (int u = 0; u < 5; u++) {
            int idx = (u << 8) + t;
            CPASYNC16(dbase + (idx << 4), src + (idx << 4));
        }
    };

    unsigned long long oacc[9];
    #pragma unroll
    for (int j = 0; j < 9; j++) oacc[j] = 0ULL;
    const int opx = t >> 4, osl = t & 15;

    stage_x(0, 0);
    stage_w(0, 0);
    CPCOMMIT();

    for (int tap = 0; tap < 9; tap++) {
        const int buf = tap & 1;
        if (tap < 8) {
            stage_x(tap + 1, buf ^ 1);
            stage_w(tap + 1, buf ^ 1);
            CPCOMMIT();
            CPWAIT(1);
        } else {
            CPWAIT(0);
        }
        __syncthreads();

        const float* svrow = sm + buf * OFF_SV1 + opx * ROWA;
        const float* swc   = sm + OFF_SW0 + buf * 5120;
        for (int i = 0; i < 16; i++) {
            int c = (i << 4) + osl;
            float sval = svrow[c];
            unsigned long long sp; PACK2(sp, sval, sval);
            const float* wrow = swc + c * 20;
            ulonglong2 w01 = *(const ulonglong2*)(wrow);
            ulonglong2 w23 = *(const ulonglong2*)(wrow + 4);
            ulonglong2 w45 = *(const ulonglong2*)(wrow + 8);
            ulonglong2 w67 = *(const ulonglong2*)(wrow + 12);
            unsigned long long w8 = *(const unsigned long long*)(wrow + 16);
            FMA2(oacc[0], sp, w01.x, oacc[0]);
            FMA2(oacc[1], sp, w01.y, oacc[1]);
            FMA2(oacc[2], sp, w23.x, oacc[2]);
            FMA2(oacc[3], sp, w23.y, oacc[3]);
            FMA2(oacc[4], sp, w45.x, oacc[4]);
            FMA2(oacc[5], sp, w45.y, oacc[5]);
            FMA2(oacc[6], sp, w67.x, oacc[6]);
            FMA2(oacc[7], sp, w67.y, oacc[7]);
            FMA2(oacc[8], sp, w8,    oacc[8]);
        }
        __syncthreads();
    }

    // reduce 16 k-slices -> offsets -> descriptors (spart aliases sw0)
    float* spart = sm + OFF_SW0;
    #pragma unroll
    for (int j = 0; j < 9; j++) {
        float lo, hi; UNPACK2(lo, hi, oacc[j]);
        spart[(((opx << 4) + osl) * 9 + j) * 2 + 0] = lo;
        spart[(((opx << 4) + osl) * 9 + j) * 2 + 1] = hi;
    }
    __syncthreads();
    if (t < 144) {
        int px = t / 9, j = t - px * 9;
        float dy = b_off[2 * j], dx = b_off[2 * j + 1];
        #pragma unroll
        for (int s = 0; s < 16; s++) {
            dy += spart[(((px << 4) + s) * 9 + j) * 2 + 0];
            dx += spart[(((px << 4) + s) * 9 + j) * 2 + 1];
        }
        float py  = dy + (float)(j / 3) + (float)(h - 1);
        float pxf = dx + (float)(j % 3) + (float)(w0 + px - 1);
        float y0f = floorf(py),  x0f = floorf(pxf);
        float wy1 = py - y0f,    wx1 = pxf - x0f;
        float wy0 = 1.f - wy1,   wx0 = 1.f - wx1;
        float vy0 = (y0f >= 0.f  && y0f <= 63.f) ? 1.f : 0.f;
        float vy1 = (y0f >= -1.f && y0f <= 62.f) ? 1.f : 0.f;
        float vx0 = (x0f >= 0.f  && x0f <= 63.f) ? 1.f : 0.f;
        float vx1 = (x0f >= -1.f && x0f <= 62.f) ? 1.f : 0.f;
        int y0 = min(max((int)y0f, 0), 63);
        int x0 = min(max((int)x0f, 0), 63);
        int y1 = min(max((int)y0f + 1, 0), 63);
        int x1 = min(max((int)x0f + 1, 0), 63);
        float4 wq = make_float4(wy0 * wx0 * vy0 * vx0, wy0 * wx1 * vy0 * vx1,
                                wy1 * wx0 * vy1 * vx0, wy1 * wx1 * vy1 * vx1);
        int4 oq = make_int4((((y0 << 6) + x0) << 10), (((y0 << 6) + x1) << 10),
                            (((y1 << 6) + x0) << 10), (((y1 << 6) + x1) << 10));
        size_t gd = (size_t)(pid0 + px) * 72 + j * 8;
        *(float4*)(g_desc + gd)     = wq;
        *(int4*)  (g_desc + gd + 4) = oq;
    }
}

// ---------------------------------------------------------------------------
// HMMA main GEMM. 128 blocks x 512 thr, 128 px x 256 o per block.
// Single barrier per chunk; cp.async + gather issued AFTER the barrier so
// no write can land while another warp still reads the previous chunk.
// ---------------------------------------------------------------------------
__global__ void __launch_bounds__(512, 1)
k_mma(float* __restrict__ out) {
    extern __shared__ char smc[];
    const int t    = threadIdx.x;
    const int pid0 = blockIdx.x * 128;
    const int b    = pid0 >> 12;
    const int hw0  = pid0 & 4095;
    const float* xb = g_xT + ((size_t)b << 20);
    unsigned smb = (unsigned)__cvta_generic_to_shared(smc);

    const int w  = t >> 5;
    const int m0 = (w & 3) * 32;        // px group (0..96)
    const int o0 = (w >> 2) * 64;       // o group (0..192)

    wmma::fragment<wmma::accumulator, 16, 16, 16, float> acc[2][4];
    #pragma unroll
    for (int mi = 0; mi < 2; mi++)
        #pragma unroll
        for (int n = 0; n < 4; n++)
            wmma::fill_fragment(acc[mi][n], 0.f);

    const int pxl = t >> 2;             // px 0..127
    const int cq  = (t & 3) * 16;       // 16 contiguous c within chunk

    auto gather = [&](int cj, int buf) {
        const float* dp = g_desc + ((size_t)(pid0 + pxl) * 9 + (cj >> 2)) * 8;
        float4 wq = *(const float4*)dp;
        int4   oq = *(const int4*)(dp + 4);
        int coff = (cj & 3) * 64 + cq;
        const float* p0 = xb + (oq.x >> 2) + coff;
        const float* p1 = xb + (oq.y >> 2) + coff;
        const float* p2 = xb + (oq.z >> 2) + coff;
        const float* p3 = xb + (oq.w >> 2) + coff;
        __nv_bfloat16* Ah = (__nv_bfloat16*)(smc + buf * 36864) + pxl * ALDA + cq;
        __nv_bfloat16* Al = Ah + 9216;
        #pragma unroll
        for (int j = 0; j < 4; j++) {
            float4 A0 = *(const float4*)(p0 + j * 4);
            float4 B0 = *(const float4*)(p1 + j * 4);
            float4 C0 = *(const float4*)(p2 + j * 4);
            float4 D0 = *(const float4*)(p3 + j * 4);
            float v0 = fmaf(wq.x, A0.x, fmaf(wq.y, B0.x, fmaf(wq.z, C0.x, wq.w * D0.x)));
            float v1 = fmaf(wq.x, A0.y, fmaf(wq.y, B0.y, fmaf(wq.z, C0.y, wq.w * D0.y)));
            float v2 = fmaf(wq.x, A0.z, fmaf(wq.y, B0.z, fmaf(wq.z, C0.z, wq.w * D0.z)));
            float v3 = fmaf(wq.x, A0.w, fmaf(wq.y, B0.w, fmaf(wq.z, C0.w, wq.w * D0.w)));
            __nv_bfloat162 h01 = __floats2bfloat162_rn(v0, v1);
            __nv_bfloat162 h23 = __floats2bfloat162_rn(v2, v3);
            float2 f01 = __bfloat1622float2(h01);
            float2 f23 = __bfloat1622float2(h23);
            __nv_bfloat162 l01 = __floats2bfloat162_rn(v0 - f01.x, v1 - f01.y);
            __nv_bfloat162 l23 = __floats2bfloat162_rn(v2 - f23.x, v3 - f23.y);
            uint2 hv, lv;
            hv.x = *(unsigned*)&h01; hv.y = *(unsigned*)&h23;
            lv.x = *(unsigned*)&l01; lv.y = *(unsigned*)&l23;
            *(uint2*)(Ah + j * 4) = hv;
            *(uint2*)(Al + j * 4) = lv;
        }
    };

    // prologue: stage B chunk 0, gather A chunk 0 (into buf 0)
    for (int idx = t; idx < 4224; idx += 512)
        CPASYNC16(smb + SMB + (idx << 4), (const char*)g_wB + (idx << 4));
    CPCOMMIT();
    gather(0, 0);

    for (int ci = 0; ci < NCHUNK; ci++) {
        const int buf = ci & 1;
        CPWAIT(0);                   // B(ci) landed (committed last iter)
        __syncthreads();             // all warps done reading buf^1

        if (ci + 1 < NCHUNK) {
            // issue next B copy + next A gather AFTER the barrier
            const char* src = (const char*)g_wB + (size_t)(ci + 1) * CHB;
            unsigned dst = smb + SMB + (unsigned)((buf ^ 1) * CHB);
            for (int idx = t; idx < 4224; idx += 512)
                CPASYNC16(dst + (idx << 4), src + (idx << 4));
            CPCOMMIT();
            gather(ci + 1, buf ^ 1); // LDG latency overlaps compute below
        }

        // ---- compute chunk ci ----
        const __nv_bfloat16* Ah = (const __nv_bfloat16*)(smc + buf * 36864);
        const __nv_bfloat16* Al = Ah + 9216;
        const __nv_bfloat16* Bh = (const __nv_bfloat16*)(smc + SMB + buf * CHB);
        const __nv_bfloat16* Bl = Bh + 16896;
        #pragma unroll
        for (int kk = 0; kk < 4; kk++) {
            int acol = kk * 16;
            int brow = kk * 16;
            wmma::fragment<wmma::matrix_a, 16, 16, 16, __nv_bfloat16,
                           wmma::row_major> ah[2], al[2];
            wmma::load_matrix_sync(ah[0], Ah + (m0)      * ALDA + acol, ALDA);
            wmma::load_matrix_sync(ah[1], Ah + (m0 + 16) * ALDA + acol, ALDA);
            wmma::load_matrix_sync(al[0], Al + (m0)      * ALDA + acol, ALDA);
            wmma::load_matrix_sync(al[1], Al + (m0 + 16) * ALDA + acol, ALDA);
            #pragma unroll
            for (int n = 0; n < 4; n++) {
                wmma::fragment<wmma::matrix_b, 16, 16, 16, __nv_bfloat16,
                               wmma::row_major> bh, bl;
                wmma::load_matrix_sync(bh, Bh + brow * ALDB + o0 + n * 16, ALDB);
                wmma::load_matrix_sync(bl, Bl + brow * ALDB + o0 + n * 16, ALDB);
                #pragma unroll
                for (int mi = 0; mi < 2; mi++) {
                    wmma::mma_sync(acc[mi][n], ah[mi], bh, acc[mi][n]);
                    wmma::mma_sync(acc[mi][n], al[mi], bh, acc[mi][n]);
                    wmma::mma_sync(acc[mi][n], ah[mi], bl, acc[mi][n]);
                }
            }
        }
    }

    #pragma unroll
    for (int mi = 0; mi < 2; mi++)
        #pragma unroll
        for (int n = 0; n < 4; n++) {
            float* p = out + (((size_t)((b << 8) + o0 + n * 16)) << 12)
                     + hw0 + m0 + mi * 16;
            wmma::store_matrix_sync(p, acc[mi][n], 4096, wmma::mem_col_major);
        }
}

// ---------------------------------------------------------------------------
// per-channel mean / inv-std
// ---------------------------------------------------------------------------
__global__ void k_stats(const float* __restrict__ out,
                        const float* __restrict__ gamma) {
    int o = blockIdx.x;
    int t = threadIdx.x, lane = t & 31, warp = t >> 5;
    float s = 0.f, s2 = 0.f;
    for (int b = 0; b < BB; b++) {
        const float4* p = (const float4*)(out + (((size_t)((b << 8) + o)) << 12));
        for (int i = t; i < 1024; i += 256) {
            float4 v = p[i];
            s += v.x + v.y + v.z + v.w;
            s2 = fmaf(v.x, v.x, s2); s2 = fmaf(v.y, v.y, s2);
            s2 = fmaf(v.z, v.z, s2); s2 = fmaf(v.w, v.w, s2);
        }
    }
    #pragma unroll
    for (int sft = 16; sft > 0; sft >>= 1) {
        s  += __shfl_xor_sync(0xffffffffu, s,  sft);
        s2 += __shfl_xor_sync(0xffffffffu, s2, sft);
    }
    __shared__ float rs[8], rs2[8];
    if (lane == 0) { rs[warp] = s; rs2[warp] = s2; }
    __syncthreads();
    if (t == 0) {
        float S = 0.f, S2 = 0.f;
        #pragma unroll
        for (int i = 0; i < 8; i++) { S += rs[i]; S2 += rs2[i]; }
        float mean = S * (1.f / 16384.f);
        float var  = S2 * (1.f / 16384.f) - mean * mean;
        g_mean[o]  = mean;
        g_scale[o] = gamma[o] * rsqrtf(var + 1e-5f);
    }
}

// ---------------------------------------------------------------------------
// in-place normalize + relu (float4)
// ---------------------------------------------------------------------------
__global__ void k_norm(float* __restrict__ out,
                       const float* __restrict__ beta) {
    int i4 = blockIdx.x * blockDim.x + threadIdx.x;
    if (i4 >= BB * OO * 1024) return;
    int o = (i4 >> 10) & 255;
    float mu = g_mean[o], sc = g_scale[o], be = beta[o];
    float4 v = ((float4*)out)[i4];
    v.x = fmaxf(fmaf(v.x - mu, sc, be), 0.f);
    v.y = fmaxf(fmaf(v.y - mu, sc, be), 0.f);
    v.z = fmaxf(fmaf(v.z - mu, sc, be), 0.f);
    v.w = fmaxf(fmaf(v.w - mu, sc, be), 0.f);
    ((float4*)out)[i4] = v;
}

// ---------------------------------------------------------------------------
extern "C" void kernel_launch(void* const* d_in, const int* in_sizes, int n_in,
                              void* d_out, int out_size) {
    const float* x     = (const float*)d_in[0];
    const float* w_off = (const float*)d_in[1];
    const float* b_off = (const float*)d_in[2];
    const float* w_def = (const float*)d_in[3];
    const float* gamma = (const float*)d_in[4];
    const float* beta  = (const float*)d_in[5];
    float* out = (float*)d_out;

    cudaFuncSetAttribute(k_offsets, cudaFuncAttributeMaxDynamicSharedMemorySize,
                         OFF_TOT * (int)sizeof(float));
    cudaFuncSetAttribute(k_mma, cudaFuncAttributeMaxDynamicSharedMemorySize,
                         SMT);

    {
        dim3 grid(4096 / 32, CC / 32, BB), blk(32, 32);
        k_transpose_x<<<grid, blk>>>(x);
    }
    k_transpose_woff<<<(18 * CC * 9 + 255) / 256, 256>>>(w_off);
    k_prep_w<<<(KK * OO) / 256, 256>>>(w_def);

    k_offsets<<<NPIX / 16, 256, OFF_TOT * sizeof(float)>>>(b_off);

    k_mma<<<NPIX / 128, 512, SMT>>>(out);

    k_stats<<<OO, 256>>>(out, gamma);
    k_norm<<<(BB * OO * 1024 + 255) / 256, 256>>>(out, beta);
}

// round 14
// speedup vs baseline: 1.0797x; 1.0797x over previous
#include <cuda_runtime.h>
#include <cuda_bf16.h>
#include <mma.h>
#include <math.h>

using namespace nvcuda;

#define BB 4
#define CC 256
#define OO 256
#define KK 2304          // C * 9
#define NPIX 16384
#define NCHUNK 36        // K chunks of 64
#define CHB 67584        // bytes per weight chunk (hi 64x528 + lo 64x528)
#define ALDB 264         // B leading dim in bf16 elements (528 B rows)
#define ALDA 72          // A chunk leading dim in bf16 elements (144 B rows)
#define ROWA 260         // k_offsets x-tile row stride (floats)

// k_mma smem bytes: A bufs 2x36864 | B bufs 2xCHB
#define SMB  73728
#define SMT  208896      // 73728 + 2*67584

// k_offsets smem (floats): sv0 0 | sv1 8320 | sw0 16640 | sw1 21760
#define OFF_SV1 8320
#define OFF_SW0 16640
#define OFF_TOT 26880    // 107520 B -> 2 CTAs/SM

// Static device scratch
__device__ float g_xT[BB * 4096 * CC];            // [b][hw][c]  16.8 MB
__device__ float g_woffT3[KK * 20];               // [k][ch pad 20]
__device__ float g_desc[NPIX * 9 * 8];            // per (pix,tap): wq f4 + oq i4
__device__ unsigned char g_wB[NCHUNK * CHB];      // bf16 hi/lo weight chunks
__device__ float g_psum[128 * OO];                // per-block partial sums
__device__ float g_psum2[128 * OO];

__device__ float g_mean[OO];
__device__ float g_scale[OO];

// ---- packed f32x2 helpers (offset kernel) ----
#define FMA2(d,a,b,c)  asm("fma.rn.f32x2 %0,%1,%2,%3;" : "=l"(d) : "l"(a),"l"(b),"l"(c))
#define PACK2(d,lo,hi) asm("mov.b64 %0,{%1,%2};" : "=l"(d) : "f"(lo),"f"(hi))
#define UNPACK2(lo,hi,s) asm("mov.b64 {%0,%1},%2;" : "=f"(lo),"=f"(hi) : "l"(s))

// ---- async copy ----
#define CPASYNC16(dst,src) asm volatile( \
    "cp.async.cg.shared.global [%0],[%1],16;" :: "r"(dst), "l"(src))
#define CPASYNC16Z(dst,src,sz) asm volatile( \
    "cp.async.cg.shared.global [%0],[%1],16,%2;" :: "r"(dst), "l"(src), "r"(sz))
#define CPCOMMIT() asm volatile("cp.async.commit_group;" ::: "memory")
#define CPWAIT(n)  asm volatile("cp.async.wait_group %0;" :: "n"(n) : "memory")

// ---------------------------------------------------------------------------
// transpose x [B][C][HW] -> xT [B][HW][C]
// ---------------------------------------------------------------------------
__global__ void k_transpose_x(const float* __restrict__ x) {
    __shared__ float tile[32][33];
    int b   = blockIdx.z;
    int hw0 = blockIdx.x * 32;
    int c0  = blockIdx.y * 32;
    tile[threadIdx.y][threadIdx.x] =
        x[(b * CC + c0 + threadIdx.y) * 4096 + hw0 + threadIdx.x];
    __syncthreads();
    g_xT[(b * 4096 + hw0 + threadIdx.y) * CC + c0 + threadIdx.x] =
        tile[threadIdx.x][threadIdx.y];
}

// ---------------------------------------------------------------------------
// transpose w_off [ch][c][tap] -> g_woffT3[(tap*256+c)*20 + ch]  (80B rows)
// ---------------------------------------------------------------------------
__global__ void k_transpose_woff(const float* __restrict__ w_off) {
    int idx = blockIdx.x * blockDim.x + threadIdx.x;
    if (idx >= 18 * CC * 9) return;
    int ch  = idx / (CC * 9);
    int r   = idx % (CC * 9);
    int c   = r / 9;
    int tap = r % 9;
    g_woffT3[(tap * CC + c) * 20 + ch] = w_off[idx];
}

// ---------------------------------------------------------------------------
// prep weights: w_def [o][c][tap] -> bf16 hi/lo chunks [k][o], 528B rows
// ---------------------------------------------------------------------------
__global__ void k_prep_w(const float* __restrict__ w_def) {
    int idx = blockIdx.x * blockDim.x + threadIdx.x;
    if (idx >= KK * OO) return;
    int o = idx & 255;
    int k = idx >> 8;
    int c = k & 255, tap = k >> 8;
    int ci = k >> 6, r = k & 63;
    float v = w_def[o * KK + c * 9 + tap];
    __nv_bfloat16 hb = __float2bfloat16_rn(v);
    float hf = __bfloat162float(hb);
    __nv_bfloat16 lb = __float2bfloat16_rn(v - hf);
    unsigned char* base = g_wB + (size_t)ci * CHB;
    *(__nv_bfloat16*)(base + r * 528 + o * 2) = hb;
    *(__nv_bfloat16*)(base + 33792 + r * 528 + o * 2) = lb;
}

// ---------------------------------------------------------------------------
// Offset conv + gather-descriptor kernel (R11-validated config: 32 px, 2 CTA).
// 512 blocks x 256 thr. Writes g_desc.
// ---------------------------------------------------------------------------
__global__ void __launch_bounds__(256, 2)
k_offsets(const float* __restrict__ b_off) {
    extern __shared__ float sm[];
    const int t    = threadIdx.x;
    const int pid0 = blockIdx.x * 32;
    const int b    = pid0 >> 12;
    const int hw0  = pid0 & 4095;
    const int h    = hw0 >> 6;
    const int w0   = hw0 & 63;
    const float* xb = g_xT + ((size_t)b << 20);
    unsigned smb = (unsigned)__cvta_generic_to_shared(sm);

    auto stage_x = [&](int tap, int buf) {
        int ty = tap / 3, kx = tap % 3 - 1;
        int y = h + ty - 1;
        bool yok = (unsigned)y < 64u;
        int yc = min(max(y, 0), 63);
        unsigned dbase = smb + (unsigned)(buf * OFF_SV1 * 4);
        #pragma unroll
        for (int u = 0; u < 8; u++) {
            int id = (u << 8) + t;
            int px = id >> 6, seg = id & 63;
            int xx = w0 + px + kx;
            bool ok = yok && ((unsigned)xx < 64u);
            int xc = min(max(xx, 0), 63);
            const char* src = (const char*)(xb + (((yc << 6) + xc) << 8)) + (seg << 4);
            unsigned d = dbase + (unsigned)((px * ROWA + (seg << 2)) << 2);
            unsigned sz = ok ? 16u : 0u;
            CPASYNC16Z(d, src, sz);
        }
    };
    auto stage_w = [&](int tap, int buf) {
        const char* src = (const char*)(g_woffT3 + tap * 5120);
        unsigned dbase = smb + (unsigned)((OFF_SW0 + buf * 5120) * 4);
        #pragma unroll
        for (int u = 0; u < 5; u++) {
            int idx = (u << 8) + t;
            CPASYNC16(dbase + (idx << 4), src + (idx << 4));
        }
    };

    unsigned long long oacc[9];
    #pragma unroll
    for (int j = 0; j < 9; j++) oacc[j] = 0ULL;
    const int opx = t >> 3, osl = t & 7;

    stage_x(0, 0);
    stage_w(0, 0);
    CPCOMMIT();

    for (int tap = 0; tap < 9; tap++) {
        const int buf = tap & 1;
        if (tap < 8) {
            stage_x(tap + 1, buf ^ 1);
            stage_w(tap + 1, buf ^ 1);
            CPCOMMIT();
            CPWAIT(1);
        } else {
            CPWAIT(0);
        }
        __syncthreads();

        const float* svrow = sm + buf * OFF_SV1 + opx * ROWA;
        const float* swc   = sm + OFF_SW0 + buf * 5120;
        for (int i = 0; i < 32; i++) {
            int c = (i << 3) + osl;
            float sval = svrow[c];
            unsigned long long sp; PACK2(sp, sval, sval);
            const float* wrow = swc + c * 20;
            ulonglong2 w01 = *(const ulonglong2*)(wrow);
            ulonglong2 w23 = *(const ulonglong2*)(wrow + 4);
            ulonglong2 w45 = *(const ulonglong2*)(wrow + 8);
            ulonglong2 w67 = *(const ulonglong2*)(wrow + 12);
            unsigned long long w8 = *(const unsigned long long*)(wrow + 16);
            FMA2(oacc[0], sp, w01.x, oacc[0]);
            FMA2(oacc[1], sp, w01.y, oacc[1]);
            FMA2(oacc[2], sp, w23.x, oacc[2]);
            FMA2(oacc[3], sp, w23.y, oacc[3]);
            FMA2(oacc[4], sp, w45.x, oacc[4]);
            FMA2(oacc[5], sp, w45.y, oacc[5]);
            FMA2(oacc[6], sp, w67.x, oacc[6]);
            FMA2(oacc[7], sp, w67.y, oacc[7]);
            FMA2(oacc[8], sp, w8,    oacc[8]);
        }
        __syncthreads();
    }

    float* spart = sm + OFF_SW0;
    #pragma unroll
    for (int j = 0; j < 9; j++) {
        float lo, hi; UNPACK2(lo, hi, oacc[j]);
        spart[(((opx << 3) + osl) * 9 + j) * 2 + 0] = lo;
        spart[(((opx << 3) + osl) * 9 + j) * 2 + 1] = hi;
    }
    __syncthreads();
    for (int idx = t; idx < 288; idx += 256) {
        int px = idx / 9, j = idx - px * 9;
        float dy = b_off[2 * j], dx = b_off[2 * j + 1];
        #pragma unroll
        for (int s = 0; s < 8; s++) {
            dy += spart[(((px << 3) + s) * 9 + j) * 2 + 0];
            dx += spart[(((px << 3) + s) * 9 + j) * 2 + 1];
        }
        float py  = dy + (float)(j / 3) + (float)(h - 1);
        float pxf = dx + (float)(j % 3) + (float)(w0 + px - 1);
        float y0f = floorf(py),  x0f = floorf(pxf);
        float wy1 = py - y0f,    wx1 = pxf - x0f;
        float wy0 = 1.f - wy1,   wx0 = 1.f - wx1;
        float vy0 = (y0f >= 0.f  && y0f <= 63.f) ? 1.f : 0.f;
        float vy1 = (y0f >= -1.f && y0f <= 62.f) ? 1.f : 0.f;
        float vx0 = (x0f >= 0.f  && x0f <= 63.f) ? 1.f : 0.f;
        float vx1 = (x0f >= -1.f && x0f <= 62.f) ? 1.f : 0.f;
        int y0 = min(max((int)y0f, 0), 63);
        int x0 = min(max((int)x0f, 0), 63);
        int y1 = min(max((int)y0f + 1, 0), 63);
        int x1 = min(max((int)x0f + 1, 0), 63);
        float4 wq = make_float4(wy0 * wx0 * vy0 * vx0, wy0 * wx1 * vy0 * vx1,
                                wy1 * wx0 * vy1 * vx0, wy1 * wx1 * vy1 * vx1);
        int4 oq = make_int4((((y0 << 6) + x0) << 10), (((y0 << 6) + x1) << 10),
                            (((y1 << 6) + x0) << 10), (((y1 << 6) + x1) << 10));
        size_t gd = (size_t)(pid0 + px) * 72 + j * 8;
        *(float4*)(g_desc + gd)     = wq;
        *(int4*)  (g_desc + gd + 4) = oq;
    }
}

// ---------------------------------------------------------------------------
// HMMA main GEMM. 128 blocks x 512 thr, 128 px x 256 o per block.
// Coalesced gather lane mapping (4 lanes of a px read 64B contiguous/corner).
// Epilogue computes per-block BN partial sums (removes full-pass k_stats).
// ---------------------------------------------------------------------------
__global__ void __launch_bounds__(512, 1)
k_mma(float* __restrict__ out) {
    extern __shared__ char smc[];
    const int t    = threadIdx.x;
    const int pid0 = blockIdx.x * 128;
    const int b    = pid0 >> 12;
    const int hw0  = pid0 & 4095;
    const float* xb = g_xT + ((size_t)b << 20);
    unsigned smb = (unsigned)__cvta_generic_to_shared(smc);

    const int w  = t >> 5;
    const int m0 = (w & 3) * 32;        // px group (0..96)
    const int o0 = (w >> 2) * 64;       // o group (0..192)

    wmma::fragment<wmma::accumulator, 16, 16, 16, float> acc[2][4];
    #pragma unroll
    for (int mi = 0; mi < 2; mi++)
        #pragma unroll
        for (int n = 0; n < 4; n++)
            wmma::fill_fragment(acc[mi][n], 0.f);

    const int pxl = t >> 2;             // px 0..127
    const int cq  = (t & 3) * 4;        // coalesced lane offset within chunk

    auto gather = [&](int cj, int buf) {
        const float* dp = g_desc + ((size_t)(pid0 + pxl) * 9 + (cj >> 2)) * 8;
        float4 wq = *(const float4*)dp;
        int4   oq = *(const int4*)(dp + 4);
        int coff = (cj & 3) * 64 + cq;
        const float* p0 = xb + (oq.x >> 2) + coff;
        const float* p1 = xb + (oq.y >> 2) + coff;
        const float* p2 = xb + (oq.z >> 2) + coff;
        const float* p3 = xb + (oq.w >> 2) + coff;
        __nv_bfloat16* Ah = (__nv_bfloat16*)(smc + buf * 36864) + pxl * ALDA + cq;
        __nv_bfloat16* Al = Ah + 9216;
        #pragma unroll
        for (int j = 0; j < 4; j++) {
            // c = coff + j*16 .. +3  (4 lanes together cover 16 consecutive c)
            float4 A0 = *(const float4*)(p0 + j * 16);
            float4 B0 = *(const float4*)(p1 + j * 16);
            float4 C0 = *(const float4*)(p2 + j * 16);
            float4 D0 = *(const float4*)(p3 + j * 16);
            float v0 = fmaf(wq.x, A0.x, fmaf(wq.y, B0.x, fmaf(wq.z, C0.x, wq.w * D0.x)));
            float v1 = fmaf(wq.x, A0.y, fmaf(wq.y, B0.y, fmaf(wq.z, C0.y, wq.w * D0.y)));
            float v2 = fmaf(wq.x, A0.z, fmaf(wq.y, B0.z, fmaf(wq.z, C0.z, wq.w * D0.z)));
            float v3 = fmaf(wq.x, A0.w, fmaf(wq.y, B0.w, fmaf(wq.z, C0.w, wq.w * D0.w)));
            __nv_bfloat162 h01 = __floats2bfloat162_rn(v0, v1);
            __nv_bfloat162 h23 = __floats2bfloat162_rn(v2, v3);
            float2 f01 = __bfloat1622float2(h01);
            float2 f23 = __bfloat1622float2(h23);
            __nv_bfloat162 l01 = __floats2bfloat162_rn(v0 - f01.x, v1 - f01.y);
            __nv_bfloat162 l23 = __floats2bfloat162_rn(v2 - f23.x, v3 - f23.y);
            uint2 hv, lv;
            hv.x = *(unsigned*)&h01; hv.y = *(unsigned*)&h23;
            lv.x = *(unsigned*)&l01; lv.y = *(unsigned*)&l23;
            *(uint2*)(Ah + j * 16) = hv;
            *(uint2*)(Al + j * 16) = lv;
        }
    };

    // prologue: stage B chunk 0, gather A chunk 0 (into buf 0)
    for (int idx = t; idx < 4224; idx += 512)
        CPASYNC16(smb + SMB + (idx << 4), (const char*)g_wB + (idx << 4));
    CPCOMMIT();
    gather(0, 0);

    for (int ci = 0; ci < NCHUNK; ci++) {
        const int buf = ci & 1;
        CPWAIT(0);                   // B(ci) landed (committed last iter)
        __syncthreads();             // all warps done reading buf^1

        if (ci + 1 < NCHUNK) {
            const char* src = (const char*)g_wB + (size_t)(ci + 1) * CHB;
            unsigned dst = smb + SMB + (unsigned)((buf ^ 1) * CHB);
            for (int idx = t; idx < 4224; idx += 512)
                CPASYNC16(dst + (idx << 4), src + (idx << 4));
            CPCOMMIT();
            gather(ci + 1, buf ^ 1); // LDG latency overlaps compute below
        }

        // ---- compute chunk ci ----
        const __nv_bfloat16* Ah = (const __nv_bfloat16*)(smc + buf * 36864);
        const __nv_bfloat16* Al = Ah + 9216;
        const __nv_bfloat16* Bh = (const __nv_bfloat16*)(smc + SMB + buf * CHB);
        const __nv_bfloat16* Bl = Bh + 16896;
        #pragma unroll
        for (int kk = 0; kk < 4; kk++) {
            int acol = kk * 16;
            int brow = kk * 16;
            wmma::fragment<wmma::matrix_a, 16, 16, 16, __nv_bfloat16,
                           wmma::row_major> ah[2], al[2];
            wmma::load_matrix_sync(ah[0], Ah + (m0)      * ALDA + acol, ALDA);
            wmma::load_matrix_sync(ah[1], Ah + (m0 + 16) * ALDA + acol, ALDA);
            wmma::load_matrix_sync(al[0], Al + (m0)      * ALDA + acol, ALDA);
            wmma::load_matrix_sync(al[1], Al + (m0 + 16) * ALDA + acol, ALDA);
            #pragma unroll
            for (int n = 0; n < 4; n++) {
                wmma::fragment<wmma::matrix_b, 16, 16, 16, __nv_bfloat16,
                               wmma::row_major> bh, bl;
                wmma::load_matrix_sync(bh, Bh + brow * ALDB + o0 + n * 16, ALDB);
                wmma::load_matrix_sync(bl, Bl + brow * ALDB + o0 + n * 16, ALDB);
                #pragma unroll
                for (int mi = 0; mi < 2; mi++) {
                    wmma::mma_sync(acc[mi][n], ah[mi], bh, acc[mi][n]);
                    wmma::mma_sync(acc[mi][n], al[mi], bh, acc[mi][n]);
                    wmma::mma_sync(acc[mi][n], ah[mi], bl, acc[mi][n]);
                }
            }
        }
    }

    #pragma unroll
    for (int mi = 0; mi < 2; mi++)
        #pragma unroll
        for (int n = 0; n < 4; n++) {
            float* p = out + (((size_t)((b << 8) + o0 + n * 16)) << 12)
                     + hw0 + m0 + mi * 16;
            wmma::store_matrix_sync(p, acc[mi][n], 4096, wmma::mem_col_major);
        }

    // ---- BN partial sums over this block's 128px x 256o tile ----
    __syncthreads();   // make all global stores visible block-wide
    {
        const int lane = t & 31;
        #pragma unroll 1
        for (int oi = 0; oi < 16; oi++) {
            int o = w * 16 + oi;
            const float* row = out + (((size_t)((b << 8) + o)) << 12) + hw0;
            float s = 0.f, s2 = 0.f;
            #pragma unroll
            for (int pg = 0; pg < 4; pg++) {
                float v = row[pg * 32 + lane];
                s += v;
                s2 = fmaf(v, v, s2);
            }
            #pragma unroll
            for (int sft = 16; sft > 0; sft >>= 1) {
                s  += __shfl_xor_sync(0xffffffffu, s,  sft);
                s2 += __shfl_xor_sync(0xffffffffu, s2, sft);
            }
            if (lane == 0) {
                g_psum[blockIdx.x * OO + o]  = s;
                g_psum2[blockIdx.x * OO + o] = s2;
            }
        }
    }
}

// ---------------------------------------------------------------------------
// finalize BN stats from per-block partials (1 block, 256 threads)
// ---------------------------------------------------------------------------
__global__ void k_finalize(const float* __restrict__ gamma) {
    int o = threadIdx.x;
    float s = 0.f, s2 = 0.f;
    for (int blk = 0; blk < 128; blk++) {
        s  += g_psum[blk * OO + o];
        s2 += g_psum2[blk * OO + o];
    }
    float mean = s * (1.f / 16384.f);
    float var  = s2 * (1.f / 16384.f) - mean * mean;
    g_mean[o]  = mean;
    g_scale[o] = gamma[o] * rsqrtf(var + 1e-5f);
}

// ---------------------------------------------------------------------------
// in-place normalize + relu (float4)
// ---------------------------------------------------------------------------
__global__ void k_norm(float* __restrict__ out,
                       const float* __restrict__ beta) {
    int i4 = blockIdx.x * blockDim.x + threadIdx.x;
    if (i4 >= BB * OO * 1024) return;
    int o = (i4 >> 10) & 255;
    float mu = g_mean[o], sc = g_scale[o], be = beta[o];
    float4 v = ((float4*)out)[i4];
    v.x = fmaxf(fmaf(v.x - mu, sc, be), 0.f);
    v.y = fmaxf(fmaf(v.y - mu, sc, be), 0.f);
    v.z = fmaxf(fmaf(v.z - mu, sc, be), 0.f);
    v.w = fmaxf(fmaf(v.w - mu, sc, be), 0.f);
    ((float4*)out)[i4] = v;
}

// ---------------------------------------------------------------------------
extern "C" void kernel_launch(void* const* d_in, const int* in_sizes, int n_in,
                              void* d_out, int out_size) {
    const float* x     = (const float*)d_in[0];
    const float* w_off = (const float*)d_in[1];
    const float* b_off = (const float*)d_in[2];
    const float* w_def = (const float*)d_in[3];
    const float* gamma = (const float*)d_in[4];
    const float* beta  = (const float*)d_in[5];
    float* out = (float*)d_out;

    cudaFuncSetAttribute(k_offsets, cudaFuncAttributeMaxDynamicSharedMemorySize,
                         OFF_TOT * (int)sizeof(float));
    cudaFuncSetAttribute(k_mma, cudaFuncAttributeMaxDynamicSharedMemorySize,
                         SMT);

    {
        dim3 grid(4096 / 32, CC / 32, BB), blk(32, 32);
        k_transpose_x<<<grid, blk>>>(x);
    }
    k_transpose_woff<<<(18 * CC * 9 + 255) / 256, 256>>>(w_off);
    k_prep_w<<<(KK * OO) / 256, 256>>>(w_def);

    k_offsets<<<NPIX / 32, 256, OFF_TOT * sizeof(float)>>>(b_off);

    k_mma<<<NPIX / 128, 512, SMT>>>(out);

    k_finalize<<<1, 256>>>(gamma);
    k_norm<<<(BB * OO * 1024 + 255) / 256, 256>>>(out, beta);
}

// round 15
// speedup vs baseline: 1.2058x; 1.1168x over previous
#include <cuda_runtime.h>
#include <cuda_bf16.h>
#include <mma.h>
#include <math.h>

using namespace nvcuda;

#define BB 4
#define CC 256
#define OO 256
#define KK 2304          // C * 9
#define NPIX 16384
#define NCHUNK 36        // K chunks of 64
#define CHB 67584        // bytes per weight chunk (hi 64x528 + lo 64x528)
#define ALDB 264         // B leading dim in bf16 elements (528 B rows)
#define ALDA 72          // A chunk leading dim in bf16 elements (144 B rows)
#define ROWA 260         // k_offsets x-tile row stride (floats)

// k_mma smem bytes: A bufs 2x36864 | B bufs 2xCHB
#define SMB  73728
#define SMT  208896      // 73728 + 2*67584

// k_offsets smem (floats): sv0 0 | sv1 8320 | sw0 16640 | sw1 21760
#define OFF_SV1 8320
#define OFF_SW0 16640
#define OFF_TOT 26880    // 107520 B -> 2 CTAs/SM

// Static device scratch
__device__ float g_xT[BB * 4096 * CC];            // [b][hw][c]  16.8 MB
__device__ float g_woffT3[KK * 20];               // [k][ch pad 20]
__device__ float g_desc[NPIX * 9 * 8];            // per (pix,tap): wq f4 + oq i4
__device__ unsigned char g_wB[NCHUNK * CHB];      // bf16 hi/lo weight chunks
__device__ float g_psum[128 * OO];                // per-block partial sums
__device__ float g_psum2[128 * OO];

__device__ float g_mean[OO];
__device__ float g_scale[OO];

// ---- packed f32x2 helpers (offset kernel) ----
#define FMA2(d,a,b,c)  asm("fma.rn.f32x2 %0,%1,%2,%3;" : "=l"(d) : "l"(a),"l"(b),"l"(c))
#define PACK2(d,lo,hi) asm("mov.b64 %0,{%1,%2};" : "=l"(d) : "f"(lo),"f"(hi))
#define UNPACK2(lo,hi,s) asm("mov.b64 {%0,%1},%2;" : "=f"(lo),"=f"(hi) : "l"(s))

// ---- async copy ----
#define CPASYNC16(dst,src) asm volatile( \
    "cp.async.cg.shared.global [%0],[%1],16;" :: "r"(dst), "l"(src))
#define CPASYNC16Z(dst,src,sz) asm volatile( \
    "cp.async.cg.shared.global [%0],[%1],16,%2;" :: "r"(dst), "l"(src), "r"(sz))
#define CPCOMMIT() asm volatile("cp.async.commit_group;" ::: "memory")
#define CPWAIT(n)  asm volatile("cp.async.wait_group %0;" :: "n"(n) : "memory")

// ---------------------------------------------------------------------------
// transpose x [B][C][HW] -> xT [B][HW][C]
// ---------------------------------------------------------------------------
__global__ void k_transpose_x(const float* __restrict__ x) {
    __shared__ float tile[32][33];
    int b   = blockIdx.z;
    int hw0 = blockIdx.x * 32;
    int c0  = blockIdx.y * 32;
    tile[threadIdx.y][threadIdx.x] =
        x[(b * CC + c0 + threadIdx.y) * 4096 + hw0 + threadIdx.x];
    __syncthreads();
    g_xT[(b * 4096 + hw0 + threadIdx.y) * CC + c0 + threadIdx.x] =
        tile[threadIdx.x][threadIdx.y];
}

// ---------------------------------------------------------------------------
// transpose w_off [ch][c][tap] -> g_woffT3[(tap*256+c)*20 + ch]  (80B rows)
// ---------------------------------------------------------------------------
__global__ void k_transpose_woff(const float* __restrict__ w_off) {
    int idx = blockIdx.x * blockDim.x + threadIdx.x;
    if (idx >= 18 * CC * 9) return;
    int ch  = idx / (CC * 9);
    int r   = idx % (CC * 9);
    int c   = r / 9;
    int tap = r % 9;
    g_woffT3[(tap * CC + c) * 20 + ch] = w_off[idx];
}

// ---------------------------------------------------------------------------
// prep weights: w_def [o][c][tap] -> bf16 hi/lo chunks [k][o], 528B rows
// ---------------------------------------------------------------------------
__global__ void k_prep_w(const float* __restrict__ w_def) {
    int idx = blockIdx.x * blockDim.x + threadIdx.x;
    if (idx >= KK * OO) return;
    int o = idx & 255;
    int k = idx >> 8;
    int c = k & 255, tap = k >> 8;
    int ci = k >> 6, r = k & 63;
    float v = w_def[o * KK + c * 9 + tap];
    __nv_bfloat16 hb = __float2bfloat16_rn(v);
    float hf = __bfloat162float(hb);
    __nv_bfloat16 lb = __float2bfloat16_rn(v - hf);
    unsigned char* base = g_wB + (size_t)ci * CHB;
    *(__nv_bfloat16*)(base + r * 528 + o * 2) = hb;
    *(__nv_bfloat16*)(base + 33792 + r * 528 + o * 2) = lb;
}

// ---------------------------------------------------------------------------
// Offset conv + gather-descriptor kernel. 512 blocks x 256 thr, 32 px/block.
// NEW mapping: warp = c-slice (weights broadcast), lane = px (LDS.128 sval).
// ---------------------------------------------------------------------------
__global__ void __launch_bounds__(256, 2)
k_offsets(const float* __restrict__ b_off) {
    extern __shared__ float sm[];
    const int t    = threadIdx.x;
    const int pid0 = blockIdx.x * 32;
    const int b    = pid0 >> 12;
    const int hw0  = pid0 & 4095;
    const int h    = hw0 >> 6;
    const int w0   = hw0 & 63;
    const float* xb = g_xT + ((size_t)b << 20);
    unsigned smb = (unsigned)__cvta_generic_to_shared(sm);

    auto stage_x = [&](int tap, int buf) {
        int ty = tap / 3, kx = tap % 3 - 1;
        int y = h + ty - 1;
        bool yok = (unsigned)y < 64u;
        int yc = min(max(y, 0), 63);
        unsigned dbase = smb + (unsigned)(buf * OFF_SV1 * 4);
        #pragma unroll
        for (int u = 0; u < 8; u++) {
            int id = (u << 8) + t;
            int px = id >> 6, seg = id & 63;
            int xx = w0 + px + kx;
            bool ok = yok && ((unsigned)xx < 64u);
            int xc = min(max(xx, 0), 63);
            const char* src = (const char*)(xb + (((yc << 6) + xc) << 8)) + (seg << 4);
            unsigned d = dbase + (unsigned)((px * ROWA + (seg << 2)) << 2);
            unsigned sz = ok ? 16u : 0u;
            CPASYNC16Z(d, src, sz);
        }
    };
    auto stage_w = [&](int tap, int buf) {
        const char* src = (const char*)(g_woffT3 + tap * 5120);
        unsigned dbase = smb + (unsigned)((OFF_SW0 + buf * 5120) * 4);
        #pragma unroll
        for (int u = 0; u < 5; u++) {
            int idx = (u << 8) + t;
            CPASYNC16(dbase + (idx << 4), src + (idx << 4));
        }
    };

    unsigned long long oacc[9];
    #pragma unroll
    for (int j = 0; j < 9; j++) oacc[j] = 0ULL;
    const int lane = t & 31;            // px
    const int wid  = t >> 5;            // c-slice (32 c per warp)

    stage_x(0, 0);
    stage_w(0, 0);
    CPCOMMIT();

    for (int tap = 0; tap < 9; tap++) {
        const int buf = tap & 1;
        if (tap < 8) {
            stage_x(tap + 1, buf ^ 1);
            stage_w(tap + 1, buf ^ 1);
            CPCOMMIT();
            CPWAIT(1);
        } else {
            CPWAIT(0);
        }
        __syncthreads();

        const float* svrow = sm + buf * OFF_SV1 + lane * ROWA;
        const float* swc   = sm + OFF_SW0 + buf * 5120;
        const int cbase0 = wid << 5;
        #pragma unroll
        for (int i = 0; i < 8; i++) {
            int cb = cbase0 + (i << 2);
            float4 s4 = *(const float4*)(svrow + cb);
            #pragma unroll
            for (int e = 0; e < 4; e++) {
                float sv = (e == 0) ? s4.x : (e == 1) ? s4.y : (e == 2) ? s4.z : s4.w;
                unsigned long long sp; PACK2(sp, sv, sv);
                const float* wrow = swc + (cb + e) * 20;   // broadcast across warp
                ulonglong2 w01 = *(const ulonglong2*)(wrow);
                ulonglong2 w23 = *(const ulonglong2*)(wrow + 4);
                ulonglong2 w45 = *(const ulonglong2*)(wrow + 8);
                ulonglong2 w67 = *(const ulonglong2*)(wrow + 12);
                unsigned long long w8 = *(const unsigned long long*)(wrow + 16);
                FMA2(oacc[0], sp, w01.x, oacc[0]);
                FMA2(oacc[1], sp, w01.y, oacc[1]);
                FMA2(oacc[2], sp, w23.x, oacc[2]);
                FMA2(oacc[3], sp, w23.y, oacc[3]);
                FMA2(oacc[4], sp, w45.x, oacc[4]);
                FMA2(oacc[5], sp, w45.y, oacc[5]);
                FMA2(oacc[6], sp, w67.x, oacc[6]);
                FMA2(oacc[7], sp, w67.y, oacc[7]);
                FMA2(oacc[8], sp, w8,    oacc[8]);
            }
        }
        __syncthreads();
    }

    // reduce 8 c-slices (warps) per px -> offsets -> descriptors
    float* spart = sm + OFF_SW0;
    #pragma unroll
    for (int j = 0; j < 9; j++) {
        float lo, hi; UNPACK2(lo, hi, oacc[j]);
        spart[(((lane << 3) + wid) * 9 + j) * 2 + 0] = lo;
        spart[(((lane << 3) + wid) * 9 + j) * 2 + 1] = hi;
    }
    __syncthreads();
    for (int idx = t; idx < 288; idx += 256) {
        int px = idx / 9, j = idx - px * 9;
        float dy = b_off[2 * j], dx = b_off[2 * j + 1];
        #pragma unroll
        for (int s = 0; s < 8; s++) {
            dy += spart[(((px << 3) + s) * 9 + j) * 2 + 0];
            dx += spart[(((px << 3) + s) * 9 + j) * 2 + 1];
        }
        float py  = dy + (float)(j / 3) + (float)(h - 1);
        float pxf = dx + (float)(j % 3) + (float)(w0 + px - 1);
        float y0f = floorf(py),  x0f = floorf(pxf);
        float wy1 = py - y0f,    wx1 = pxf - x0f;
        float wy0 = 1.f - wy1,   wx0 = 1.f - wx1;
        float vy0 = (y0f >= 0.f  && y0f <= 63.f) ? 1.f : 0.f;
        float vy1 = (y0f >= -1.f && y0f <= 62.f) ? 1.f : 0.f;
        float vx0 = (x0f >= 0.f  && x0f <= 63.f) ? 1.f : 0.f;
        float vx1 = (x0f >= -1.f && x0f <= 62.f) ? 1.f : 0.f;
        int y0 = min(max((int)y0f, 0), 63);
        int x0 = min(max((int)x0f, 0), 63);
        int y1 = min(max((int)y0f + 1, 0), 63);
        int x1 = min(max((int)x0f + 1, 0), 63);
        float4 wq = make_float4(wy0 * wx0 * vy0 * vx0, wy0 * wx1 * vy0 * vx1,
                                wy1 * wx0 * vy1 * vx0, wy1 * wx1 * vy1 * vx1);
        int4 oq = make_int4((((y0 << 6) + x0) << 10), (((y0 << 6) + x1) << 10),
                            (((y1 << 6) + x0) << 10), (((y1 << 6) + x1) << 10));
        size_t gd = (size_t)(pid0 + px) * 72 + j * 8;
        *(float4*)(g_desc + gd)     = wq;
        *(int4*)  (g_desc + gd + 4) = oq;
    }
}

// ---------------------------------------------------------------------------
// HMMA main GEMM (R14-validated). 128 blocks x 512 thr, 128 px x 256 o.
// ---------------------------------------------------------------------------
__global__ void __launch_bounds__(512, 1)
k_mma(float* __restrict__ out) {
    extern __shared__ char smc[];
    const int t    = threadIdx.x;
    const int pid0 = blockIdx.x * 128;
    const int b    = pid0 >> 12;
    const int hw0  = pid0 & 4095;
    const float* xb = g_xT + ((size_t)b << 20);
    unsigned smb = (unsigned)__cvta_generic_to_shared(smc);

    const int w  = t >> 5;
    const int m0 = (w & 3) * 32;        // px group (0..96)
    const int o0 = (w >> 2) * 64;       // o group (0..192)

    wmma::fragment<wmma::accumulator, 16, 16, 16, float> acc[2][4];
    #pragma unroll
    for (int mi = 0; mi < 2; mi++)
        #pragma unroll
        for (int n = 0; n < 4; n++)
            wmma::fill_fragment(acc[mi][n], 0.f);

    const int pxl = t >> 2;             // px 0..127
    const int cq  = (t & 3) * 4;        // coalesced lane offset within chunk

    auto gather = [&](int cj, int buf) {
        const float* dp = g_desc + ((size_t)(pid0 + pxl) * 9 + (cj >> 2)) * 8;
        float4 wq = *(const float4*)dp;
        int4   oq = *(const int4*)(dp + 4);
        int coff = (cj & 3) * 64 + cq;
        const float* p0 = xb + (oq.x >> 2) + coff;
        const float* p1 = xb + (oq.y >> 2) + coff;
        const float* p2 = xb + (oq.z >> 2) + coff;
        const float* p3 = xb + (oq.w >> 2) + coff;
        __nv_bfloat16* Ah = (__nv_bfloat16*)(smc + buf * 36864) + pxl * ALDA + cq;
        __nv_bfloat16* Al = Ah + 9216;
        #pragma unroll
        for (int j = 0; j < 4; j++) {
            float4 A0 = *(const float4*)(p0 + j * 16);
            float4 B0 = *(const float4*)(p1 + j * 16);
            float4 C0 = *(const float4*)(p2 + j * 16);
            float4 D0 = *(const float4*)(p3 + j * 16);
            float v0 = fmaf(wq.x, A0.x, fmaf(wq.y, B0.x, fmaf(wq.z, C0.x, wq.w * D0.x)));
            float v1 = fmaf(wq.x, A0.y, fmaf(wq.y, B0.y, fmaf(wq.z, C0.y, wq.w * D0.y)));
            float v2 = fmaf(wq.x, A0.z, fmaf(wq.y, B0.z, fmaf(wq.z, C0.z, wq.w * D0.z)));
            float v3 = fmaf(wq.x, A0.w, fmaf(wq.y, B0.w, fmaf(wq.z, C0.w, wq.w * D0.w)));
            __nv_bfloat162 h01 = __floats2bfloat162_rn(v0, v1);
            __nv_bfloat162 h23 = __floats2bfloat162_rn(v2, v3);
            float2 f01 = __bfloat1622float2(h01);
            float2 f23 = __bfloat1622float2(h23);
            __nv_bfloat162 l01 = __floats2bfloat162_rn(v0 - f01.x, v1 - f01.y);
            __nv_bfloat162 l23 = __floats2bfloat162_rn(v2 - f23.x, v3 - f23.y);
            uint2 hv, lv;
            hv.x = *(unsigned*)&h01; hv.y = *(unsigned*)&h23;
            lv.x = *(unsigned*)&l01; lv.y = *(unsigned*)&l23;
            *(uint2*)(Ah + j * 16) = hv;
            *(uint2*)(Al + j * 16) = lv;
        }
    };

    for (int idx = t; idx < 4224; idx += 512)
        CPASYNC16(smb + SMB + (idx << 4), (const char*)g_wB + (idx << 4));
    CPCOMMIT();
    gather(0, 0);

    for (int ci = 0; ci < NCHUNK; ci++) {
        const int buf = ci & 1;
        CPWAIT(0);
        __syncthreads();

        if (ci + 1 < NCHUNK) {
            const char* src = (const char*)g_wB + (size_t)(ci + 1) * CHB;
            unsigned dst = smb + SMB + (unsigned)((buf ^ 1) * CHB);
            for (int idx = t; idx < 4224; idx += 512)
                CPASYNC16(dst + (idx << 4), src + (idx << 4));
            CPCOMMIT();
            gather(ci + 1, buf ^ 1);
        }

        const __nv_bfloat16* Ah = (const __nv_bfloat16*)(smc + buf * 36864);
        const __nv_bfloat16* Al = Ah + 9216;
        const __nv_bfloat16* Bh = (const __nv_bfloat16*)(smc + SMB + buf * CHB);
        const __nv_bfloat16* Bl = Bh + 16896;
        #pragma unroll
        for (int kk = 0; kk < 4; kk++) {
            int acol = kk * 16;
            int brow = kk * 16;
            wmma::fragment<wmma::matrix_a, 16, 16, 16, __nv_bfloat16,
                           wmma::row_major> ah[2], al[2];
            wmma::load_matrix_sync(ah[0], Ah + (m0)      * ALDA + acol, ALDA);
            wmma::load_matrix_sync(ah[1], Ah + (m0 + 16) * ALDA + acol, ALDA);
            wmma::load_matrix_sync(al[0], Al + (m0)      * ALDA + acol, ALDA);
            wmma::load_matrix_sync(al[1], Al + (m0 + 16) * ALDA + acol, ALDA);
            #pragma unroll
            for (int n = 0; n < 4; n++) {
                wmma::fragment<wmma::matrix_b, 16, 16, 16, __nv_bfloat16,
                               wmma::row_major> bh, bl;
                wmma::load_matrix_sync(bh, Bh + brow * ALDB + o0 + n * 16, ALDB);
                wmma::load_matrix_sync(bl, Bl + brow * ALDB + o0 + n * 16, ALDB);
                #pragma unroll
                for (int mi = 0; mi < 2; mi++) {
                    wmma::mma_sync(acc[mi][n], ah[mi], bh, acc[mi][n]);
                    wmma::mma_sync(acc[mi][n], al[mi], bh, acc[mi][n]);
                    wmma::mma_sync(acc[mi][n], ah[mi], bl, acc[mi][n]);
                }
            }
        }
    }

    #pragma unroll
    for (int mi = 0; mi < 2; mi++)
        #pragma unroll
        for (int n = 0; n < 4; n++) {
            float* p = out + (((size_t)((b << 8) + o0 + n * 16)) << 12)
                     + hw0 + m0 + mi * 16;
            wmma::store_matrix_sync(p, acc[mi][n], 4096, wmma::mem_col_major);
        }

    // ---- BN partial sums over this block's 128px x 256o tile ----
    __syncthreads();
    {
        const int lane = t & 31;
        #pragma unroll 1
        for (int oi = 0; oi < 16; oi++) {
            int o = w * 16 + oi;
            const float* row = out + (((size_t)((b << 8) + o)) << 12) + hw0;
            float s = 0.f, s2 = 0.f;
            #pragma unroll
            for (int pg = 0; pg < 4; pg++) {
                float v = row[pg * 32 + lane];
                s += v;
                s2 = fmaf(v, v, s2);
            }
            #pragma unroll
            for (int sft = 16; sft > 0; sft >>= 1) {
                s  += __shfl_xor_sync(0xffffffffu, s,  sft);
                s2 += __shfl_xor_sync(0xffffffffu, s2, sft);
            }
            if (lane == 0) {
                g_psum[blockIdx.x * OO + o]  = s;
                g_psum2[blockIdx.x * OO + o] = s2;
            }
        }
    }
}

// ---------------------------------------------------------------------------
// finalize BN stats from per-block partials (1 block, 256 threads)
// ---------------------------------------------------------------------------
__global__ void k_finalize(const float* __restrict__ gamma) {
    int o = threadIdx.x;
    float s = 0.f, s2 = 0.f;
    for (int blk = 0; blk < 128; blk++) {
        s  += g_psum[blk * OO + o];
        s2 += g_psum2[blk * OO + o];
    }
    float mean = s * (1.f / 16384.f);
    float var  = s2 * (1.f / 16384.f) - mean * mean;
    g_mean[o]  = mean;
    g_scale[o] = gamma[o] * rsqrtf(var + 1e-5f);
}

// ---------------------------------------------------------------------------
// in-place normalize + relu (float4)
// ---------------------------------------------------------------------------
__global__ void k_norm(float* __restrict__ out,
                       const float* __restrict__ beta) {
    int i4 = blockIdx.x * blockDim.x + threadIdx.x;
    if (i4 >= BB * OO * 1024) return;
    int o = (i4 >> 10) & 255;
    float mu = g_mean[o], sc = g_scale[o], be = beta[o];
    float4 v = ((float4*)out)[i4];
    v.x = fmaxf(fmaf(v.x - mu, sc, be), 0.f);
    v.y = fmaxf(fmaf(v.y - mu, sc, be), 0.f);
    v.z = fmaxf(fmaf(v.z - mu, sc, be), 0.f);
    v.w = fmaxf(fmaf(v.w - mu, sc, be), 0.f);
    ((float4*)out)[i4] = v;
}

// ---------------------------------------------------------------------------
extern "C" void kernel_launch(void* const* d_in, const int* in_sizes, int n_in,
                              void* d_out, int out_size) {
    const float* x     = (const float*)d_in[0];
    const float* w_off = (const float*)d_in[1];
    const float* b_off = (const float*)d_in[2];
    const float* w_def = (const float*)d_in[3];
    const float* gamma = (const float*)d_in[4];
    const float* beta  = (const float*)d_in[5];
    float* out = (float*)d_out;

    cudaFuncSetAttribute(k_offsets, cudaFuncAttributeMaxDynamicSharedMemorySize,
                         OFF_TOT * (int)sizeof(float));
    cudaFuncSetAttribute(k_mma, cudaFuncAttributeMaxDynamicSharedMemorySize,
                         SMT);

    {
        dim3 grid(4096 / 32, CC / 32, BB), blk(32, 32);
        k_transpose_x<<<grid, blk>>>(x);
    }
    k_transpose_woff<<<(18 * CC * 9 + 255) / 256, 256>>>(w_off);
    k_prep_w<<<(KK * OO) / 256, 256>>>(w_def);

    k_offsets<<<NPIX / 32, 256, OFF_TOT * sizeof(float)>>>(b_off);

    k_mma<<<NPIX / 128, 512, SMT>>>(out);

    k_finalize<<<1, 256>>>(gamma);
    k_norm<<<(BB * OO * 1024 + 255) / 256, 256>>>(out, beta);
}